// round 3
// baseline (speedup 1.0000x reference)
#include <cuda_runtime.h>
#include <math.h>

#define NPTS   65536
#define NN     34
#define KP     15
#define INF    64
#define OUTF   64
#define OFFD   60
#define EXTENTF 0.5f
#define PPB    4
#define TPB    256
#define NBLK   (NPTS / PPB)      // 16384
#define NI     (KP * INF)        // 960
#define NI4    (NI / 4)          // 240

// ---------------- device scratch (no allocations allowed) ----------------
__device__ __align__(16) float g_owT[NI4 * 64 * 4];   // blocked transpose of offset_weight, cols 60..63 stay 0
__device__ __align__(16) float g_wT [NI4 * 64 * 4];   // blocked transpose of weight
__device__ float g_psum  [NBLK * OUTF];
__device__ float g_psumsq[NBLK * OUTF];
__device__ __align__(16) float g_scale[OUTF];
__device__ __align__(16) float g_shift[OUTF];

// packed fp32x2 FMA: acc = a*b + acc (Blackwell FFMA2)
__device__ __forceinline__ void f2fma(float2 &acc, float2 a, float2 b) {
    asm("{\n\t"
        ".reg .b64 ra, rb, rc;\n\t"
        "mov.b64 ra, {%2, %3};\n\t"
        "mov.b64 rb, {%4, %5};\n\t"
        "mov.b64 rc, {%0, %1};\n\t"
        "fma.rn.f32x2 rc, ra, rb, rc;\n\t"
        "mov.b64 {%0, %1}, rc;\n\t"
        "}"
        : "+f"(acc.x), "+f"(acc.y)
        : "f"(a.x), "f"(a.y), "f"(b.x), "f"(b.y));
}

// ---------------- prep: blocked transposes of the two weight matrices ----------------
__global__ void prep_kernel(const float* __restrict__ ow, const float* __restrict__ w) {
    int t = blockIdx.x * blockDim.x + threadIdx.x;
    int stride = gridDim.x * blockDim.x;
    // offset_weight: [K,IN,60] linear (i*60+d), i = k*64+c
    for (int idx = t; idx < NI * OFFD; idx += stride) {
        int i = idx / OFFD, d = idx - i * OFFD;
        g_owT[((i >> 2) * 64 + d) * 4 + (i & 3)] = ow[idx];
    }
    // weight: [K,IN,64] linear (i*64+o)
    for (int idx = t; idx < NI * OUTF; idx += stride) {
        int i = idx / OUTF, o = idx - i * OUTF;
        g_wT[((i >> 2) * 64 + o) * 4 + (i & 3)] = w[idx];
    }
}

// ---------------- main fused kernel: 4 points per CTA ----------------
__global__ __launch_bounds__(TPB) void kpconv_kernel(
    const float* __restrict__ query,
    const float* __restrict__ support,
    const int*   __restrict__ nbr,
    const float* __restrict__ feat,
    const float* __restrict__ obias,
    const float* __restrict__ kpts,
    float*       __restrict__ out)
{
    __shared__ __align__(16) float s_w  [PPB][NN][20];   // influence weights (15 used + pad), stride 20 -> conflict-free STS.128
    __shared__ __align__(16) float s_pts[PPB][NN][4];    // neighbor offsets
    __shared__ int                 s_idx[PPB][NN];
    __shared__ __align__(16) float s_wf [PPB][NI];       // [k*64+c]
    __shared__ __align__(16) float s_red[PPB][4][64];    // cross-slot reduction scratch
    __shared__ __align__(16) float s_f0 [PPB][64];       // f0 / later reused for x
    __shared__ __align__(16) float s_dkp[PPB][KP][4];    // deformed kp xyz + modulation

    const int tid = threadIdx.x;
    const int p   = tid >> 6;      // point slot 0..3
    const int t   = tid & 63;      // channel / lane role
    const int n   = blockIdx.x * PPB + p;

    // ===== Phase A: rigid influence weights =====
    if (t < NN) {
        float qx = query[n*3+0], qy = query[n*3+1], qz = query[n*3+2];
        int id = nbr[n*NN + t];
        s_idx[p][t] = id;
        float px = support[id*3+0] - qx;
        float py = support[id*3+1] - qy;
        float pz = support[id*3+2] - qz;
        s_pts[p][t][0] = px; s_pts[p][t][1] = py; s_pts[p][t][2] = pz;
        float wl[16];
        #pragma unroll
        for (int k = 0; k < KP; k++) {
            float dx = px - kpts[k*3+0];
            float dy = py - kpts[k*3+1];
            float dz = pz - kpts[k*3+2];
            float sq = dx*dx + dy*dy + dz*dz;
            wl[k] = fmaxf(1.0f - 2.0f * sqrtf(sq), 0.0f);
        }
        wl[15] = 0.0f;
        #pragma unroll
        for (int j = 0; j < 4; j++)
            *(float4*)&s_w[p][t][j*4] = make_float4(wl[j*4+0], wl[j*4+1], wl[j*4+2], wl[j*4+3]);
    }
    __syncthreads();

    // ===== Phase B: wf0[k] = sum_a w0[a,k] * feat[a, c=t]  (regs, packed FMA) =====
    {
        float2 wf[8];
        #pragma unroll
        for (int k = 0; k < 8; k++) wf[k] = make_float2(0.f, 0.f);
        #pragma unroll 2
        for (int a = 0; a < NN; a++) {
            float f = feat[s_idx[p][a] * INF + t];
            float2 ff = make_float2(f, f);
            const float4* wr = (const float4*)&s_w[p][a][0];
            float4 w0 = wr[0], w1 = wr[1], w2 = wr[2], w3 = wr[3];
            f2fma(wf[0], make_float2(w0.x, w0.y), ff);
            f2fma(wf[1], make_float2(w0.z, w0.w), ff);
            f2fma(wf[2], make_float2(w1.x, w1.y), ff);
            f2fma(wf[3], make_float2(w1.z, w1.w), ff);
            f2fma(wf[4], make_float2(w2.x, w2.y), ff);
            f2fma(wf[5], make_float2(w2.z, w2.w), ff);
            f2fma(wf[6], make_float2(w3.x, w3.y), ff);
            f2fma(wf[7], make_float2(w3.z, w3.w), ff);
        }
        #pragma unroll
        for (int k = 0; k < KP; k++) {
            float v = (k & 1) ? wf[k >> 1].y : wf[k >> 1].x;
            s_wf[p][k * INF + t] = v;
        }
    }
    __syncthreads();

    // ===== Phase C: f0[d] = bias[d] + sum_i wf0[i] * ow[i,d]; slot p covers i-quarter for all 4 points =====
    {
        float2 acc[PPB][2];
        #pragma unroll
        for (int pp = 0; pp < PPB; pp++) { acc[pp][0] = make_float2(0.f,0.f); acc[pp][1] = make_float2(0.f,0.f); }
        #pragma unroll 2
        for (int it = 0; it < 60; it++) {
            int i4 = p * 60 + it;
            float4 w4 = *(const float4*)&g_owT[(i4 * 64 + t) * 4];
            #pragma unroll
            for (int pp = 0; pp < PPB; pp++) {
                float4 v4 = *(const float4*)&s_wf[pp][i4 * 4];
                f2fma(acc[pp][0], make_float2(v4.x, v4.y), make_float2(w4.x, w4.y));
                f2fma(acc[pp][1], make_float2(v4.z, v4.w), make_float2(w4.z, w4.w));
            }
        }
        #pragma unroll
        for (int pp = 0; pp < PPB; pp++)
            s_red[pp][p][t] = acc[pp][0].x + acc[pp][0].y + acc[pp][1].x + acc[pp][1].y;
    }
    __syncthreads();
    if (t < OFFD) {
        float f0 = obias[t] + s_red[p][0][t] + s_red[p][1][t] + s_red[p][2][t] + s_red[p][3][t];
        s_f0[p][t] = f0;
    }
    __syncthreads();

    // ===== offsets + modulations -> deformed kernel points =====
    if (t < KP) {
        float ox = s_f0[p][3*t+0] * EXTENTF;
        float oy = s_f0[p][3*t+1] * EXTENTF;
        float oz = s_f0[p][3*t+2] * EXTENTF;
        s_dkp[p][t][0] = kpts[t*3+0] + ox;
        s_dkp[p][t][1] = kpts[t*3+1] + oy;
        s_dkp[p][t][2] = kpts[t*3+2] + oz;
        s_dkp[p][t][3] = 2.0f / (1.0f + expf(-s_f0[p][45 + t]));   // modulation
    }
    __syncthreads();

    // ===== Phase A2: deformed influence weights =====
    if (t < NN) {
        float px = s_pts[p][t][0], py = s_pts[p][t][1], pz = s_pts[p][t][2];
        float wl[16];
        #pragma unroll
        for (int k = 0; k < KP; k++) {
            float dx = px - s_dkp[p][k][0];
            float dy = py - s_dkp[p][k][1];
            float dz = pz - s_dkp[p][k][2];
            float sq = dx*dx + dy*dy + dz*dz;
            wl[k] = fmaxf(1.0f - 2.0f * sqrtf(sq), 0.0f);
        }
        wl[15] = 0.0f;
        #pragma unroll
        for (int j = 0; j < 4; j++)
            *(float4*)&s_w[p][t][j*4] = make_float4(wl[j*4+0], wl[j*4+1], wl[j*4+2], wl[j*4+3]);
    }
    __syncthreads();

    // ===== Phase D: wf[k] = mod[k] * sum_a w[a,k] * feat[a, c=t] =====
    {
        float2 wf[8];
        #pragma unroll
        for (int k = 0; k < 8; k++) wf[k] = make_float2(0.f, 0.f);
        #pragma unroll 2
        for (int a = 0; a < NN; a++) {
            float f = feat[s_idx[p][a] * INF + t];
            float2 ff = make_float2(f, f);
            const float4* wr = (const float4*)&s_w[p][a][0];
            float4 w0 = wr[0], w1 = wr[1], w2 = wr[2], w3 = wr[3];
            f2fma(wf[0], make_float2(w0.x, w0.y), ff);
            f2fma(wf[1], make_float2(w0.z, w0.w), ff);
            f2fma(wf[2], make_float2(w1.x, w1.y), ff);
            f2fma(wf[3], make_float2(w1.z, w1.w), ff);
            f2fma(wf[4], make_float2(w2.x, w2.y), ff);
            f2fma(wf[5], make_float2(w2.z, w2.w), ff);
            f2fma(wf[6], make_float2(w3.x, w3.y), ff);
            f2fma(wf[7], make_float2(w3.z, w3.w), ff);
        }
        #pragma unroll
        for (int k = 0; k < KP; k++) {
            float v = (k & 1) ? wf[k >> 1].y : wf[k >> 1].x;
            s_wf[p][k * INF + t] = v * s_dkp[p][k][3];
        }
    }
    __syncthreads();

    // ===== Phase E: x[o] = sum_i wf[i] * weight[i,o] =====
    {
        float2 acc[PPB][2];
        #pragma unroll
        for (int pp = 0; pp < PPB; pp++) { acc[pp][0] = make_float2(0.f,0.f); acc[pp][1] = make_float2(0.f,0.f); }
        #pragma unroll 2
        for (int it = 0; it < 60; it++) {
            int i4 = p * 60 + it;
            float4 w4 = *(const float4*)&g_wT[(i4 * 64 + t) * 4];
            #pragma unroll
            for (int pp = 0; pp < PPB; pp++) {
                float4 v4 = *(const float4*)&s_wf[pp][i4 * 4];
                f2fma(acc[pp][0], make_float2(v4.x, v4.y), make_float2(w4.x, w4.y));
                f2fma(acc[pp][1], make_float2(v4.z, v4.w), make_float2(w4.z, w4.w));
            }
        }
        #pragma unroll
        for (int pp = 0; pp < PPB; pp++)
            s_red[pp][p][t] = acc[pp][0].x + acc[pp][0].y + acc[pp][1].x + acc[pp][1].y;
    }
    __syncthreads();
    {
        float x = s_red[p][0][t] + s_red[p][1][t] + s_red[p][2][t] + s_red[p][3][t];
        out[n * OUTF + t] = x;
        s_f0[p][t] = x;                    // reuse as x buffer for BN partials
    }
    __syncthreads();
    if (tid < OUTF) {
        float a = s_f0[0][tid], b = s_f0[1][tid], c = s_f0[2][tid], d = s_f0[3][tid];
        g_psum  [blockIdx.x * OUTF + tid] = a + b + c + d;
        g_psumsq[blockIdx.x * OUTF + tid] = a*a + b*b + c*c + d*d;
    }
}

// ---------------- BN stats: one block per channel (deterministic fixed-order reduce) ----------------
__global__ void stats_kernel(const float* __restrict__ gamma, const float* __restrict__ beta) {
    int o = blockIdx.x;
    int tid = threadIdx.x;
    float s = 0.f, s2 = 0.f;
    for (int j = tid; j < NBLK; j += blockDim.x) {
        s  += g_psum  [j * OUTF + o];
        s2 += g_psumsq[j * OUTF + o];
    }
    __shared__ float sh[256], sh2[256];
    sh[tid] = s; sh2[tid] = s2;
    __syncthreads();
    for (int st = 128; st > 0; st >>= 1) {
        if (tid < st) { sh[tid] += sh[tid + st]; sh2[tid] += sh2[tid + st]; }
        __syncthreads();
    }
    if (tid == 0) {
        float mean = sh[0]  / (float)NPTS;
        float var  = sh2[0] / (float)NPTS - mean * mean;
        float sc   = rsqrtf(var + 1e-6f) * gamma[o];
        g_scale[o] = sc;
        g_shift[o] = beta[o] - mean * sc;
    }
}

// ---------------- BN apply + LeakyReLU ----------------
__global__ void bn_kernel(float* __restrict__ out) {
    const int total4 = NPTS * OUTF / 4;
    for (int i = blockIdx.x * blockDim.x + threadIdx.x; i < total4; i += gridDim.x * blockDim.x) {
        float4 v = ((float4*)out)[i];
        int ch = (i & 15) * 4;
        float4 sc = *(const float4*)&g_scale[ch];
        float4 sh = *(const float4*)&g_shift[ch];
        v.x = v.x * sc.x + sh.x;  v.x = v.x >= 0.f ? v.x : 0.1f * v.x;
        v.y = v.y * sc.y + sh.y;  v.y = v.y >= 0.f ? v.y : 0.1f * v.y;
        v.z = v.z * sc.z + sh.z;  v.z = v.z >= 0.f ? v.z : 0.1f * v.z;
        v.w = v.w * sc.w + sh.w;  v.w = v.w >= 0.f ? v.w : 0.1f * v.w;
        ((float4*)out)[i] = v;
    }
}

// ---------------- launch ----------------
extern "C" void kernel_launch(void* const* d_in, const int* in_sizes, int n_in,
                              void* d_out, int out_size) {
    const float* query   = (const float*)d_in[0];
    const float* support = (const float*)d_in[1];
    const int*   nbr     = (const int*)  d_in[2];
    const float* feat    = (const float*)d_in[3];
    const float* weight  = (const float*)d_in[4];
    const float* ow      = (const float*)d_in[5];
    const float* obias   = (const float*)d_in[6];
    const float* gamma   = (const float*)d_in[7];
    const float* beta    = (const float*)d_in[8];
    const float* kpts    = (const float*)d_in[9];
    float* out = (float*)d_out;

    prep_kernel<<<120, 512>>>(ow, weight);
    kpconv_kernel<<<NBLK, TPB>>>(query, support, nbr, feat, obias, kpts, out);
    stats_kernel<<<OUTF, 256>>>(gamma, beta);
    bn_kernel<<<2048, 256>>>(out);
}